// round 17
// baseline (speedup 1.0000x reference)
#include <cuda_runtime.h>
#include <math.h>
#include <cstdint>

typedef unsigned long long ull;

#define BB 8
#define NN 64
#define HH 128
#define HEADS 4
#define HD 128
#define INNER 512
#define EE 8
#define NEdg 4032
#define LL 8
#define ROWS (BB*NN)   // 512
#define SPLITJ 8
#define JB (NN/SPLITJ) // 8
#define NB 256
#define NT 256

// ---- proj smem: A[64][68] uint2 (hi,lo) + B[68-stride] uint2 ----
#define APITCH 68
#define A_U2 (64*APITCH)          // 4352 uint2 (69632B total with B)

// ---- attn smem layout (byte offsets) ----
#define KP_OFF  0                 // Kp  [72][68] uint2 = 39168B  (rows 0-63 K, 64-71 eW)
#define QP_OFF  39168             // Qp  [8][68] uint2  = 4352B
#define VT_OFF  43520             // VTp [128][44] uint2 = 45056B (kp 0-31 V, 32-35 eW, 36-39 zero)
#define SS_OFF  88576             // sS  [8][68] float  = 2176B
#define SQE_OFF 90752             // sQE [8][8] float   = 256B
#define SAE_OFF 91008             // sAE [8][8] float   = 256B
#define AA_OFF  91264             // Aa  [8][44] uint2  = 2816B
#define SMEM_BYTES 94080

// ---------- persistent scratch ----------
__device__ float g_bufA[ROWS*HH];
__device__ float g_bufB[ROWS*HH];
__device__ float g_q[ROWS*INNER];
__device__ float g_k[ROWS*INNER];
__device__ float g_v[ROWS*INNER];
__device__ float g_P[ROWS*EE];
__device__ float g_D[ROWS*EE];
__device__ int   g_eid[NN*NN];
__device__ unsigned g_bar_cnt;
__device__ unsigned g_bar_gen;

// ---------- helpers ----------
__device__ __forceinline__ unsigned pkbf(float a, float b) {
    unsigned r; asm("cvt.rn.bf16x2.f32 %0, %1, %2;" : "=r"(r) : "f"(b), "f"(a)); return r;
}
__device__ __forceinline__ uint2 bfsplit(float f0, float f1) {
    unsigned h = pkbf(f0, f1);
    float r0 = f0 - __uint_as_float(h << 16);
    float r1 = f1 - __uint_as_float(h & 0xffff0000u);
    return make_uint2(h, pkbf(r0, r1));
}
__device__ __forceinline__ void mma_bf16(float* d, unsigned a0, unsigned a1, unsigned a2, unsigned a3,
                                         unsigned b0, unsigned b1) {
    asm volatile("mma.sync.aligned.m16n8k16.row.col.f32.bf16.bf16.f32 "
                 "{%0,%1,%2,%3}, {%4,%5,%6,%7}, {%8,%9}, {%0,%1,%2,%3};"
                 : "+f"(d[0]), "+f"(d[1]), "+f"(d[2]), "+f"(d[3])
                 : "r"(a0), "r"(a1), "r"(a2), "r"(a3), "r"(b0), "r"(b1));
}

// ---------- grid barriers (release-only fast path; ld.cg coherence) ----------
__device__ __forceinline__ void grid_sync_fast() {
    __syncthreads();
    if (threadIdx.x == 0) {
        __threadfence();   // release
        unsigned gen = *(volatile unsigned*)&g_bar_gen;
        if (atomicAdd(&g_bar_cnt, 1u) == NB - 1) {
            *(volatile unsigned*)&g_bar_cnt = 0u;
            __threadfence();
            *(volatile unsigned*)&g_bar_gen = gen + 1u;
        } else {
            while (*(volatile unsigned*)&g_bar_gen == gen) { __nanosleep(32); }
        }
    }
    __syncthreads();
}
__device__ __forceinline__ void grid_sync_init() {
    __syncthreads();
    if (threadIdx.x == 0) {
        __threadfence();
        unsigned gen = *(volatile unsigned*)&g_bar_gen;
        if (atomicAdd(&g_bar_cnt, 1u) == NB - 1) {
            *(volatile unsigned*)&g_bar_cnt = 0u;
            __threadfence();
            *(volatile unsigned*)&g_bar_gen = gen + 1u;
        } else {
            while (*(volatile unsigned*)&g_bar_gen == gen) { __nanosleep(32); }
        }
        __threadfence();   // acquire (once)
    }
    __syncthreads();
}

__global__ void __launch_bounds__(NT, 2) mega(
    const float* __restrict__ noise, const float* __restrict__ edge_attr,
    const int* __restrict__ eidx,
    const float* __restrict__ fc1_w, const float* __restrict__ fc1_b,
    const float* __restrict__ qw, const float* __restrict__ qb,
    const float* __restrict__ kw, const float* __restrict__ kb,
    const float* __restrict__ vw, const float* __restrict__ vb,
    const float* __restrict__ ew,
    const float* __restrict__ sw, const float* __restrict__ sb,
    const float* __restrict__ atom_w, const float* __restrict__ atom_b,
    const float* __restrict__ other_w, const float* __restrict__ other_b,
    const float* __restrict__ efw, const float* __restrict__ efb,
    float* __restrict__ out)
{
    extern __shared__ __align__(16) float smem[];
    char* smemc = (char*)smem;
    const int t = threadIdx.x, blk = blockIdx.x;
    const int w = t >> 5, lane = t & 31;
    const int g = lane >> 2, q = lane & 3;

    // ================= init =================
    if (blk < BB && t < HH) {
        float acc = fc1_b[t];
        #pragma unroll 4
        for (int i = 0; i < 128; i++) acc += noise[blk*128 + i] * fc1_w[i*HH + t];
        acc = fmaxf(acc, 0.f);
        for (int n = 0; n < NN; n++) g_bufA[(blk*NN + n)*HH + t] = acc;
    }
    { int e = blk*NT + t; if (e < NEdg) g_eid[eidx[e]*NN + eidx[NEdg + e]] = e; }
    grid_sync_init();

    float* xin = g_bufA;
    float* xout = g_bufB;

    for (int l = 0; l < LL; l++) {
        // ============ proj: mma.sync bf16 hi/lo 3-pass, 64x64xK128 tiles (208 jobs) ============
        if (blk < 208) {
            uint2* Ap = (uint2*)smem;
            uint2* Bp = ((uint2*)smem) + A_U2;
            int ct = blk % 26, rt = blk / 26;
            const float* W; const float* bias; int ld, coff; float* outp;
            if (ct < 8)       { W = qw + l*HH*INNER; bias = qb + l*INNER; ld = INNER; coff = ct*64;      outp = g_q; }
            else if (ct < 16) { W = kw + l*HH*INNER; bias = kb + l*INNER; ld = INNER; coff = (ct-8)*64;  outp = g_k; }
            else if (ct < 24) { W = vw + l*HH*INNER; bias = vb + l*INNER; ld = INNER; coff = (ct-16)*64; outp = g_v; }
            else              { W = sw + l*HH*HH;    bias = sb + l*HH;    ld = HH;    coff = (ct-24)*64; outp = xout; }
            int r0 = rt * 64;

            {   // stage A: relu(xin) -> (hi,lo) pairs
                int row = t >> 2, qq = t & 3;
                const float* xr = &xin[(r0 + row)*HH];
                #pragma unroll
                for (int i = 0; i < 16; i++) {
                    int kp = qq + 4*i;
                    float2 v = __ldcg((const float2*)&xr[2*kp]);
                    Ap[row*APITCH + kp] = bfsplit(fmaxf(v.x, 0.f), fmaxf(v.y, 0.f));
                }
            }
            {   // stage B: W -> (hi,lo) k-pair rows
                int n = t & 63, cg = t >> 6;
                const float* wp = &W[coff + n];
                #pragma unroll
                for (int i = 0; i < 16; i++) {
                    int kp = cg + 4*i;
                    float f0 = wp[(size_t)(2*kp)*ld];
                    float f1 = wp[(size_t)(2*kp + 1)*ld];
                    Bp[kp*APITCH + n] = bfsplit(f0, f1);
                }
            }
            __syncthreads();

            {   // mainloop: warp w -> m-tile mt (16 rows), n-half nh (4 n8-tiles)
                int mt = w & 3, nh = w >> 2;
                float acc[4][4] = {};
                const uint2* Abase = Ap + (mt*16)*APITCH;
                #pragma unroll
                for (int s = 0; s < 8; s++) {
                    int kp0 = 8*s + q;
                    uint2 a0 = Abase[g*APITCH + kp0];
                    uint2 a1 = Abase[(g+8)*APITCH + kp0];
                    uint2 a2 = Abase[g*APITCH + kp0 + 4];
                    uint2 a3 = Abase[(g+8)*APITCH + kp0 + 4];
                    #pragma unroll
                    for (int nt = 0; nt < 4; nt++) {
                        int n = nh*32 + nt*8 + g;
                        uint2 b0 = Bp[kp0*APITCH + n];
                        uint2 b1 = Bp[(kp0+4)*APITCH + n];
                        mma_bf16(acc[nt], a0.x, a1.x, a2.x, a3.x, b0.x, b1.x);
                        mma_bf16(acc[nt], a0.x, a1.x, a2.x, a3.x, b0.y, b1.y);
                        mma_bf16(acc[nt], a0.y, a1.y, a2.y, a3.y, b0.x, b1.x);
                    }
                }
                int row0 = r0 + mt*16 + g;
                #pragma unroll
                for (int nt = 0; nt < 4; nt++) {
                    int col = coff + nh*32 + nt*8 + 2*q;
                    float2 bv = *(const float2*)&bias[col];
                    float2 o0 = {acc[nt][0] + bv.x, acc[nt][1] + bv.y};
                    float2 o1 = {acc[nt][2] + bv.x, acc[nt][3] + bv.y};
                    *(float2*)&outp[(size_t)row0*ld + col] = o0;
                    *(float2*)&outp[(size_t)(row0+8)*ld + col] = o1;
                }
            }
        }
        grid_sync_fast();

        // ============ attn: fully tensor-core (scores+qe / aggV+aggE via mma) ============
        {
            uint2* Kp  = (uint2*)(smemc + KP_OFF);    // [72][68]
            uint2* Qp  = (uint2*)(smemc + QP_OFF);    // [8][68]
            uint2* VTp = (uint2*)(smemc + VT_OFF);    // [128][44]
            float (*sS)[68] = (float(*)[68])(smemc + SS_OFF);
            float* sQE = (float*)(smemc + SQE_OFF);
            float* sAE = (float*)(smemc + SAE_OFF);
            uint2* Aa  = (uint2*)(smemc + AA_OFF);    // [8][44]

            int jseg = blk & 7;
            int h = (blk >> 3) & 3;
            int b = blk >> 5;
            int jbase = jseg * JB;
            const float scale = 0.08838834764831845f;  // 1/sqrt(128)

            // ---- stage K rows 0-63 ----
            {
                int n = t >> 2, qq = t & 3;
                const float* kr = &g_k[(b*NN + n)*INNER + h*HD];
                #pragma unroll
                for (int i = 0; i < 8; i++) {
                    int f4i = qq + 4*i;                    // float4 index (2 kp)
                    float4 v = __ldcg((const float4*)&kr[f4i*4]);
                    Kp[n*68 + 2*f4i]     = bfsplit(v.x, v.y);
                    Kp[n*68 + 2*f4i + 1] = bfsplit(v.z, v.w);
                }
            }
            // ---- stage eW into Kp rows 64-71 ----
            {
                int f = t >> 5, c = t & 31;
                float4 v = *(const float4*)&ew[((size_t)l*EE + f)*INNER + h*HD + c*4];
                Kp[(64+f)*68 + 2*c]     = bfsplit(v.x, v.y);
                Kp[(64+f)*68 + 2*c + 1] = bfsplit(v.z, v.w);
            }
            // ---- stage Q rows 0-7 ----
            {
                int row = t >> 5, c = t & 31;
                float4 v = __ldcg((const float4*)&g_q[(b*NN + jbase + row)*INNER + h*HD + c*4]);
                Qp[row*68 + 2*c]     = bfsplit(v.x, v.y);
                Qp[row*68 + 2*c + 1] = bfsplit(v.z, v.w);
            }
            // ---- stage V transposed: VTp[d][kp] = (V[2kp][d], V[2kp+1][d]) ----
            {
                int kp = t >> 3, dc = t & 7;
                const float* v0 = &g_v[(size_t)(b*NN + 2*kp)*INNER + h*HD];
                const float* v1 = v0 + INNER;
                #pragma unroll
                for (int dd = 0; dd < 4; dd++) {
                    int d0 = dc*16 + dd*4;
                    float4 a = __ldcg((const float4*)&v0[d0]);
                    float4 c4 = __ldcg((const float4*)&v1[d0]);
                    VTp[(d0+0)*44 + kp] = bfsplit(a.x, c4.x);
                    VTp[(d0+1)*44 + kp] = bfsplit(a.y, c4.y);
                    VTp[(d0+2)*44 + kp] = bfsplit(a.z, c4.z);
                    VTp[(d0+3)*44 + kp] = bfsplit(a.w, c4.w);
                }
            }
            // ---- stage eW^T into VTp kp 32-35; zero kp 36-39 ----
            {
                int fp = t & 3, dg = t >> 2;
                const float* e0 = &ew[((size_t)l*EE + 2*fp)*INNER + h*HD];
                const float* e1 = e0 + INNER;
                #pragma unroll
                for (int dd = 0; dd < 2; dd++) {
                    int d = dg*2 + dd;
                    VTp[d*44 + 32 + fp] = bfsplit(e0[d], e1[d]);
                }
                int dz = t >> 1, kz = 36 + 2*(t & 1);
                VTp[dz*44 + kz]     = make_uint2(0u, 0u);
                VTp[dz*44 + kz + 1] = make_uint2(0u, 0u);
            }
            __syncthreads();

            // ---- scores MMA: warp w -> src tile w (rows 8w..8w+7); warp 7 also qe tile ----
            float sc[4] = {0.f, 0.f, 0.f, 0.f};
            {
                #pragma unroll
                for (int s = 0; s < 8; s++) {
                    uint2 a0 = Qp[g*68 + 8*s + q];
                    uint2 a2 = Qp[g*68 + 8*s + q + 4];
                    uint2 b0 = Kp[(8*w + g)*68 + 8*s + q];
                    uint2 b1 = Kp[(8*w + g)*68 + 8*s + q + 4];
                    mma_bf16(sc, a0.x, 0u, a2.x, 0u, b0.x, b1.x);
                    mma_bf16(sc, a0.x, 0u, a2.x, 0u, b0.y, b1.y);
                    mma_bf16(sc, a0.y, 0u, a2.y, 0u, b0.x, b1.x);
                }
            }
            if (w == 7) {
                float qc[4] = {0.f, 0.f, 0.f, 0.f};
                #pragma unroll
                for (int s = 0; s < 8; s++) {
                    uint2 a0 = Qp[g*68 + 8*s + q];
                    uint2 a2 = Qp[g*68 + 8*s + q + 4];
                    uint2 b0 = Kp[(64 + g)*68 + 8*s + q];
                    uint2 b1 = Kp[(64 + g)*68 + 8*s + q + 4];
                    mma_bf16(qc, a0.x, 0u, a2.x, 0u, b0.x, b1.x);
                    mma_bf16(qc, a0.x, 0u, a2.x, 0u, b0.y, b1.y);
                    mma_bf16(qc, a0.y, 0u, a2.y, 0u, b0.x, b1.x);
                }
                sQE[g*8 + 2*q]     = qc[0];
                sQE[g*8 + 2*q + 1] = qc[1];
            }
            __syncthreads();

            // ---- edge bias + mask + scale; write sS ----
            {
                int j = jbase + g;
                int i0 = 8*w + 2*q, i1 = i0 + 1;
                const float* eab = edge_attr + (size_t)b * NEdg * EE;
                int e0 = (i0 == j) ? 0 : g_eid[i0*NN + j];
                int e1 = (i1 == j) ? 0 : g_eid[i1*NN + j];
                float4 p0a = *(const float4*)&eab[e0*EE];
                float4 p0b = *(const float4*)&eab[e0*EE + 4];
                float4 p1a = *(const float4*)&eab[e1*EE];
                float4 p1b = *(const float4*)&eab[e1*EE + 4];
                const float* qe = &sQE[g*8];
                float bs0 = p0a.x*qe[0] + p0a.y*qe[1] + p0a.z*qe[2] + p0a.w*qe[3]
                          + p0b.x*qe[4] + p0b.y*qe[5] + p0b.z*qe[6] + p0b.w*qe[7];
                float bs1 = p1a.x*qe[0] + p1a.y*qe[1] + p1a.z*qe[2] + p1a.w*qe[3]
                          + p1b.x*qe[4] + p1b.y*qe[5] + p1b.z*qe[6] + p1b.w*qe[7];
                float2 sv;
                sv.x = (i0 == j) ? -1e30f : (sc[0] + bs0) * scale;
                sv.y = (i1 == j) ? -1e30f : (sc[1] + bs1) * scale;
                *(float2*)&sS[g][i0] = sv;
            }
            __syncthreads();

            // ---- softmax + aggE: warp w owns row w ----
            {
                int jg = jbase + w;
                float s1 = sS[w][lane], s2 = sS[w][lane + 32];
                float m = fmaxf(s1, s2);
                #pragma unroll
                for (int o = 1; o < 32; o <<= 1) m = fmaxf(m, __shfl_xor_sync(0xffffffffu, m, o));
                float x1 = __expf(s1 - m), x2 = __expf(s2 - m);
                float sum = x1 + x2;
                #pragma unroll
                for (int o = 1; o < 32; o <<= 1) sum += __shfl_xor_sync(0xffffffffu, sum, o);
                float inv = 1.f / sum;
                float al1 = x1 * inv, al2 = x2 * inv;
                sS[w][lane] = al1;
                sS[w][lane + 32] = al2;
                int i1 = lane, i2 = lane + 32;
                const float* eab = edge_attr + (size_t)b * NEdg * EE;
                int e1 = (i1 == jg) ? 0 : g_eid[i1*NN + jg];
                int e2 = (i2 == jg) ? 0 : g_eid[i2*NN + jg];
                float4 ea1a = *(const float4*)&eab[e1*EE];
                float4 ea1b = *(const float4*)&eab[e1*EE + 4];
                float4 ea2a = *(const float4*)&eab[e2*EE];
                float4 ea2b = *(const float4*)&eab[e2*EE + 4];
                float ea1[8] = {ea1a.x, ea1a.y, ea1a.z, ea1a.w, ea1b.x, ea1b.y, ea1b.z, ea1b.w};
                float ea2[8] = {ea2a.x, ea2a.y, ea2a.z, ea2a.w, ea2b.x, ea2b.y, ea2b.z, ea2b.w};
                #pragma unroll
                for (int f = 0; f < 8; f++) {
                    float v = al1*ea1[f] + al2*ea2[f];
                    #pragma unroll
                    for (int o = 1; o < 32; o <<= 1) v += __shfl_xor_sync(0xffffffffu, v, o);
                    if (lane == 0) sAE[w*8 + f] = v;
                }
            }
            __syncthreads();

            // ---- restage alpha/aggE into Aa (bf16 hi/lo pairs over k=src) ----
            {
                int ar = t >> 5, akp = t & 31;
                float2 av = *(const float2*)&sS[ar][2*akp];
                Aa[ar*44 + akp] = bfsplit(av.x, av.y);
                if (t < 32) {
                    int r2 = t >> 2, fp = t & 3;
                    Aa[r2*44 + 32 + fp] = bfsplit(sAE[r2*8 + 2*fp], sAE[r2*8 + 2*fp + 1]);
                } else if (t < 64) {
                    int r3 = (t - 32) >> 2, kp = 36 + (t & 3);
                    Aa[r3*44 + kp] = make_uint2(0u, 0u);
                }
            }
            __syncthreads();

            // ---- aggV MMA: warp w -> d-tiles {w, w+8}; k = 80 (5 ksteps incl. aggE cols) ----
            {
                float ac0[4] = {0.f, 0.f, 0.f, 0.f};
                float ac1[4] = {0.f, 0.f, 0.f, 0.f};
                int n0 = 8*w + g, n1 = 8*(w+8) + g;
                #pragma unroll
                for (int s = 0; s < 5; s++) {
                    uint2 a0 = Aa[g*44 + 8*s + q];
                    uint2 a2 = Aa[g*44 + 8*s + q + 4];
                    uint2 b0 = VTp[n0*44 + 8*s + q];
                    uint2 b1 = VTp[n0*44 + 8*s + q + 4];
                    mma_bf16(ac0, a0.x, 0u, a2.x, 0u, b0.x, b1.x);
                    mma_bf16(ac0, a0.x, 0u, a2.x, 0u, b0.y, b1.y);
                    mma_bf16(ac0, a0.y, 0u, a2.y, 0u, b0.x, b1.x);
                    uint2 c0 = VTp[n1*44 + 8*s + q];
                    uint2 c1 = VTp[n1*44 + 8*s + q + 4];
                    mma_bf16(ac1, a0.x, 0u, a2.x, 0u, c0.x, c1.x);
                    mma_bf16(ac1, a0.x, 0u, a2.x, 0u, c0.y, c1.y);
                    mma_bf16(ac1, a0.y, 0u, a2.y, 0u, c0.x, c1.x);
                }
                int j = jbase + g;
                float* xo = &xout[(size_t)(b*NN + j)*HH];
                int d0 = 8*w + 2*q, d1 = 8*(w+8) + 2*q;
                atomicAdd(&xo[d0],     0.25f*ac0[0]);
                atomicAdd(&xo[d0 + 1], 0.25f*ac0[1]);
                atomicAdd(&xo[d1],     0.25f*ac1[0]);
                atomicAdd(&xo[d1 + 1], 0.25f*ac1[1]);
            }
        }
        grid_sync_fast();
        float* tmp = xin; xin = xout; xout = tmp;
    }

    // ================= node head + P/D (2 nodes per block) =================
    {
        float* xr   = smem;
        float* outs = smem + 256;
        float* red  = smem + 336;
        int sub = t >> 7, tl = t & 127;
        int node = blk*2 + sub;
        xr[sub*128 + tl] = fmaxf(__ldcg(&xin[node*128 + tl]), 0.f);
        __syncthreads();
        if (tl < 40) {
            const float* xp = &xr[sub*128];
            float acc;
            if (tl < 9)       { acc = atom_b[tl];  for (int d = 0; d < HH; d++) acc += xp[d]*atom_w[d*9+tl]; }
            else if (tl < 24) { int c = tl-9;  acc = other_b[c]; for (int d = 0; d < HH; d++) acc += xp[d]*other_w[d*15+c]; }
            else if (tl < 32) { int f = tl-24; acc = 0.f; for (int d = 0; d < HH; d++) acc += xp[d]*efw[d*EE+f]; }
            else              { int f = tl-32; acc = 0.f; for (int d = 0; d < HH; d++) acc += xp[d]*efw[(128+d)*EE+f]; }
            outs[sub*40 + tl] = acc;
        }
        __syncthreads();
        if (tl == 0) {
            float m = -1e30f;
            for (int a = 0; a < 9; a++) m = fmaxf(m, outs[sub*40+a]);
            float s = 0.f;
            for (int a = 0; a < 9; a++) s += __expf(outs[sub*40+a]-m);
            red[sub*2] = m; red[sub*2+1] = s;
        }
        __syncthreads();
        if (tl < 9) {
            float p = __expf(outs[sub*40+tl]-red[sub*2]) / red[sub*2+1];
            out[node*24 + tl] = 1.f/(1.f + __expf(-p));
        } else if (tl < 24) {
            float o = 1.f/(1.f + __expf(-outs[sub*40+tl]));
            out[node*24 + tl] = 1.f/(1.f + __expf(-o));
        } else if (tl < 32) {
            g_P[node*EE + (tl-24)] = outs[sub*40+tl];
        } else if (tl < 40) {
            g_D[node*EE + (tl-32)] = outs[sub*40+tl];
        }
    }
    grid_sync_fast();

    // ================= edge head =================
    if (t < 126) {
        int eg = blk*126 + t;     // 256*126 = 32256
        int b = eg / NEdg, e = eg % NEdg;
        int s = eidx[e], d = eidx[NEdg + e];
        float4 Pa = __ldcg((const float4*)&g_P[(b*NN + s)*EE]);
        float4 Pb = __ldcg((const float4*)&g_P[(b*NN + s)*EE + 4]);
        float4 Da = __ldcg((const float4*)&g_D[(b*NN + d)*EE]);
        float4 Db = __ldcg((const float4*)&g_D[(b*NN + d)*EE + 4]);
        float P[8] = {Pa.x, Pa.y, Pa.z, Pa.w, Pb.x, Pb.y, Pb.z, Pb.w};
        float D[8] = {Da.x, Da.y, Da.z, Da.w, Db.x, Db.y, Db.z, Db.w};
        float* o = out + (size_t)ROWS*24 + (size_t)eg*EE;
        #pragma unroll
        for (int f = 0; f < EE; f++) {
            float v = P[f] + D[f] + efb[f];
            o[f] = 1.f/(1.f + __expf(-v));
        }
    }
}

extern "C" void kernel_launch(void* const* d_in, const int* in_sizes, int n_in,
                              void* d_out, int out_size) {
    const float* noise     = (const float*)d_in[0];
    const float* edge_attr = (const float*)d_in[1];
    const int*   edge_index= (const int*)  d_in[2];
    const float* fc1_w     = (const float*)d_in[3];
    const float* fc1_b     = (const float*)d_in[4];
    const float* q_w       = (const float*)d_in[5];
    const float* q_b       = (const float*)d_in[6];
    const float* k_w       = (const float*)d_in[7];
    const float* k_b       = (const float*)d_in[8];
    const float* v_w       = (const float*)d_in[9];
    const float* v_b       = (const float*)d_in[10];
    const float* e_w       = (const float*)d_in[11];
    const float* skip_w    = (const float*)d_in[12];
    const float* skip_b    = (const float*)d_in[13];
    const float* atom_w    = (const float*)d_in[14];
    const float* atom_b    = (const float*)d_in[15];
    const float* other_w   = (const float*)d_in[16];
    const float* other_b   = (const float*)d_in[17];
    const float* efw       = (const float*)d_in[18];
    const float* efb       = (const float*)d_in[19];
    float* out = (float*)d_out;

    cudaFuncSetAttribute(mega, cudaFuncAttributeMaxDynamicSharedMemorySize, SMEM_BYTES);
    cudaFuncSetAttribute(mega, cudaFuncAttributePreferredSharedMemoryCarveout, 100);
    mega<<<NB, NT, SMEM_BYTES>>>(noise, edge_attr, edge_index, fc1_w, fc1_b,
                     q_w, q_b, k_w, k_b, v_w, v_b, e_w, skip_w, skip_b,
                     atom_w, atom_b, other_w, other_b, efw, efb, out);
}